// round 6
// baseline (speedup 1.0000x reference)
#include <cuda_runtime.h>
#include <cuda_bf16.h>

// Problem constants
#define NB 16
#define NC 256
#define HW 4096
#define GB 8                         // batches per L2-resident group
#define NGROUPS (NB / GB)
#define NCHUNK 32                    // se chunks per (f,b)
#define CPIX (HW / NCHUNK)           // 128 pixels per se block
#define ENH_ELEMS (NB * NC * HW)     // 16777216
#define ENT_ELEMS (NB * HW)          // 65536 per map

// ---------------- scratch (device globals; no allocation) ----------------
__device__ float g_pooled[2][NB][NC];
__device__ float g_cw[2][NB][NC];
__device__ float g_se[2][NB][HW];
__device__ float g_psum[2][NB][NCHUNK];
__device__ float g_psq[2][NB][NCHUNK];

// ---------------- entropy: log(p+eps) - (1-p)*log(1-p+eps), p=sigmoid(x) ---
// softplus form: log p = -softplus(-x), log(1-p) = -softplus(x)
// softplus(x) = max(x,0) + log(1+exp(-|x|)).  3 MUFU: EX2, LG2, RCP.
__device__ __forceinline__ float entropy_val(float x) {
    float a = fabsf(x);
    float t = __expf(-a);                  // e^{-|x|} in (0,1]
    float l = __logf(1.0f + t);            // log(1+e^{-|x|})
    float inv = __fdividef(1.0f, 1.0f + t);
    bool pos = (x >= 0.0f);
    float p      = pos ? inv        : t * inv;   // sigmoid(x)
    float logp   = pos ? -l         : (x - l);   // log p
    float log1mp = pos ? (-x - l)   : -l;        // log (1-p)
    return logp - (1.0f - p) * log1mp;
}

// ---------------- K1: pooled[b,c] = mean over HW (per group) ----------------
__global__ void k_pool(const float* __restrict__ vis, const float* __restrict__ text,
                       int b0) {
    int id = blockIdx.x;              // 0 .. 2*GB*NC-1
    int f  = id / (GB * NC);
    int bc = id % (GB * NC);
    int b  = b0 + (bc >> 8);
    int c  = bc & 255;
    const float* feat = f ? text : vis;
    const float4* src = (const float4*)(feat + ((size_t)b * NC + c) * HW);
    float acc = 0.0f;
    #pragma unroll 4
    for (int i = threadIdx.x; i < HW / 4; i += 128) {
        float4 v = src[i];
        acc += (v.x + v.y) + (v.z + v.w);
    }
    #pragma unroll
    for (int o = 16; o; o >>= 1) acc += __shfl_xor_sync(0xffffffffu, acc, o);
    __shared__ float s[4];
    if ((threadIdx.x & 31) == 0) s[threadIdx.x >> 5] = acc;
    __syncthreads();
    if (threadIdx.x == 0) {
        float tsum = (s[0] + s[1]) + (s[2] + s[3]);
        g_pooled[f][b][c] = tsum * (1.0f / HW);
    }
}

// ---------------- K2: cw = sigmoid(relu(pooled@w1+b1)@w2+b2) (per group) ----
__global__ void k_mlp(const float* __restrict__ w1, const float* __restrict__ b1,
                      const float* __restrict__ w2, const float* __restrict__ b2,
                      int b0) {
    int f = blockIdx.x / GB;
    int b = b0 + blockIdx.x % GB;
    __shared__ float sp[NC];
    __shared__ float sh[64];
    sp[threadIdx.x] = g_pooled[f][b][threadIdx.x];
    __syncthreads();
    if (threadIdx.x < 64) {
        float acc = b1[threadIdx.x];
        #pragma unroll 8
        for (int i = 0; i < NC; i++) acc = fmaf(sp[i], w1[i * 64 + threadIdx.x], acc);
        sh[threadIdx.x] = fmaxf(acc, 0.0f);
    }
    __syncthreads();
    float acc = b2[threadIdx.x];
    #pragma unroll 8
    for (int j = 0; j < 64; j++) acc = fmaf(sh[j], w2[j * NC + threadIdx.x], acc);
    g_cw[f][b][threadIdx.x] = __fdividef(1.0f, 1.0f + __expf(-acc));
}

// ---------------- K3: se[b,hw] = sum_c ent(feat)*cw + block partials --------
__global__ void k_se(const float* __restrict__ vis, const float* __restrict__ text,
                     int b0) {
    int bid   = blockIdx.x;           // 0 .. 2*GB*NCHUNK-1  (512 blocks/group)
    int f     = bid / (GB * NCHUNK);
    int rem   = bid % (GB * NCHUNK);
    int b     = b0 + rem / NCHUNK;
    int chunk = rem % NCHUNK;
    int tid   = threadIdx.x;          // 128 threads, 1 pixel each

    __shared__ float scw[NC];
    scw[tid]       = g_cw[f][b][tid];
    scw[tid + 128] = g_cw[f][b][tid + 128];
    __syncthreads();

    int pix = chunk * CPIX + tid;
    const float* feat = (f ? text : vis) + (size_t)b * NC * HW + pix;

    float acc = 0.0f;
    #pragma unroll 8
    for (int c = 0; c < NC; c++) {
        float x = __ldg(feat + (size_t)c * HW);
        acc = fmaf(entropy_val(x), scw[c], acc);
    }
    g_se[f][b][pix] = acc;

    float s = acc, q = acc * acc;
    #pragma unroll
    for (int o = 16; o; o >>= 1) {
        s += __shfl_xor_sync(0xffffffffu, s, o);
        q += __shfl_xor_sync(0xffffffffu, q, o);
    }
    __shared__ float ss[4], sq[4];
    if ((tid & 31) == 0) { ss[tid >> 5] = s; sq[tid >> 5] = q; }
    __syncthreads();
    if (tid == 0) {
        float S = (ss[0] + ss[1]) + (ss[2] + ss[3]);
        float Q = (sq[0] + sq[1]) + (sq[2] + sq[3]);
        g_psum[f][b][chunk] = S;
        g_psq [f][b][chunk] = Q;
    }
}

// ---------------- K4: enhanced blend, inline threshold (per group) ----------
// mask uses raw se vs mean(se)*0.5 — identical to comparing normalized values
// since the per-batch L2 norm is a positive scalar.
__global__ void k_out(const float* __restrict__ vis, const float* __restrict__ text,
                      float* __restrict__ out, int b0) {
    int idx4l = blockIdx.x * 256 + threadIdx.x;     // 0 .. GB*NC*1024-1
    int pix4  = idx4l & 1023;                       // HW/4 = 1024
    int b     = b0 + (idx4l >> 18);                 // / (NC*1024)
    size_t idx4 = (size_t)b * (NC * 1024) + (idx4l & (NC * 1024 - 1));

    float Sv = 0.0f, St = 0.0f;
    #pragma unroll
    for (int i = 0; i < NCHUNK; i++) { Sv += g_psum[0][b][i]; St += g_psum[1][b][i]; }
    float thr_v = Sv * (0.5f / HW);
    float thr_t = St * (0.5f / HW);

    float4 sev = ((const float4*)g_se[0][b])[pix4];
    float4 set = ((const float4*)g_se[1][b])[pix4];
    float4 v = __ldcs(((const float4*)vis) + idx4);   // last use: stream
    float4 t = __ldcs(((const float4*)text) + idx4);
    float4 o;
    o.x = (sev.x < thr_v) ? v.x : ((set.x < thr_t) ? t.x : 0.0f);
    o.y = (sev.y < thr_v) ? v.y : ((set.y < thr_t) ? t.y : 0.0f);
    o.z = (sev.z < thr_v) ? v.z : ((set.z < thr_t) ? t.z : 0.0f);
    o.w = (sev.w < thr_v) ? v.w : ((set.w < thr_t) ? t.w : 0.0f);
    __stcs(((float4*)out) + idx4, o);                 // write-once: stream
}

// ---------------- K5: normalized entropy maps, inline inv-norm --------------
__global__ void k_ent(float* __restrict__ out) {
    int idx = blockIdx.x * 256 + threadIdx.x;       // 0 .. 131071
    int f   = idx >> 16;
    int rem = idx & 65535;
    int b   = rem >> 12;
    int pix = rem & 4095;
    float Q = 0.0f;
    #pragma unroll
    for (int i = 0; i < NCHUNK; i++) Q += g_psq[f][b][i];
    float inv = 1.0f / fmaxf(sqrtf(Q), 1e-12f);
    out[ENH_ELEMS + idx] = g_se[f][b][pix] * inv;
}

// ---------------- launch ----------------
extern "C" void kernel_launch(void* const* d_in, const int* in_sizes, int n_in,
                              void* d_out, int out_size) {
    const float* vis  = (const float*)d_in[0];
    const float* text = (const float*)d_in[1];
    const float* w1   = (const float*)d_in[2];
    const float* b1   = (const float*)d_in[3];
    const float* w2   = (const float*)d_in[4];
    const float* b2   = (const float*)d_in[5];
    float* out = (float*)d_out;

    // L2-resident batch groups: each group's 64 MB of features is read from
    // DRAM once (k_pool) and re-read from L2 by k_se and k_out.
    for (int g = 0; g < NGROUPS; g++) {
        int b0 = g * GB;
        k_pool<<<2 * GB * NC, 128>>>(vis, text, b0);
        k_mlp <<<2 * GB, NC>>>(w1, b1, w2, b2, b0);
        k_se  <<<2 * GB * NCHUNK, 128>>>(vis, text, b0);
        k_out <<<GB * NC * HW / 4 / 256, 256>>>(vis, text, out, b0);
    }
    k_ent<<<2 * ENT_ELEMS / 256, 256>>>(out);
}

// round 7
// speedup vs baseline: 2.0148x; 2.0148x over previous
#include <cuda_runtime.h>
#include <cuda_bf16.h>

// Problem constants
#define NB 16
#define NC 256
#define HW 4096
#define ENH_ELEMS (NB * NC * HW)       // 16777216
#define ENT_ELEMS (NB * HW)            // 65536 per map

// ---------------- scratch (device globals; no allocation) ----------------
__device__ float g_pooled[2][NB][NC];
__device__ float g_cw[2][NB][NC];
__device__ float g_se[2][NB][HW];
__device__ float g_psum[2][NB][16];
__device__ float g_psq[2][NB][16];
__device__ float g_thr[2][NB];
__device__ float g_inv[2][NB];

// ---------------- entropy: log(p+eps) - (1-p)*log(1-p+eps), p=sigmoid(x) ---
// softplus form: log p = -softplus(-x), log(1-p) = -softplus(x)
// softplus(x) = max(x,0) + log(1+exp(-|x|)).  3 MUFU: EX2, LG2, RCP.
__device__ __forceinline__ float entropy_val(float x) {
    float a = fabsf(x);
    float t = __expf(-a);                  // e^{-|x|} in (0,1]
    float l = __logf(1.0f + t);            // log(1+e^{-|x|})
    float inv = __fdividef(1.0f, 1.0f + t);
    bool pos = (x >= 0.0f);
    float p      = pos ? inv        : t * inv;   // sigmoid(x)
    float logp   = pos ? -l         : (x - l);   // log p
    float log1mp = pos ? (-x - l)   : -l;        // log (1-p)
    return logp - (1.0f - p) * log1mp;
}

// ---------------- K1: pooled[b,c] = mean over HW (ascending slab order) -----
__global__ void k_pool(const float* __restrict__ vis, const float* __restrict__ text) {
    int id = blockIdx.x;              // 0..8191, ascending addresses
    int f  = id >> 12;                // /4096 (= NB*NC)
    int bc = id & 4095;
    const float* feat = f ? text : vis;
    const float4* src = (const float4*)(feat + (size_t)bc * HW);
    float acc = 0.0f;
    #pragma unroll 4
    for (int i = threadIdx.x; i < HW / 4; i += 128) {
        float4 v = src[i];
        acc += (v.x + v.y) + (v.z + v.w);
    }
    #pragma unroll
    for (int o = 16; o; o >>= 1) acc += __shfl_xor_sync(0xffffffffu, acc, o);
    __shared__ float s[4];
    if ((threadIdx.x & 31) == 0) s[threadIdx.x >> 5] = acc;
    __syncthreads();
    if (threadIdx.x == 0) {
        float tsum = (s[0] + s[1]) + (s[2] + s[3]);
        int b = bc >> 8, c = bc & 255;
        g_pooled[f][b][c] = tsum * (1.0f / HW);
    }
}

// ---------------- K2: cw = sigmoid(relu(pooled@w1+b1)@w2+b2) ----------------
__global__ void k_mlp(const float* __restrict__ w1, const float* __restrict__ b1,
                      const float* __restrict__ w2, const float* __restrict__ b2) {
    int f = blockIdx.x >> 4, b = blockIdx.x & 15;
    __shared__ float sp[NC];
    __shared__ float sh[64];
    sp[threadIdx.x] = g_pooled[f][b][threadIdx.x];
    __syncthreads();
    if (threadIdx.x < 64) {
        float acc = b1[threadIdx.x];
        #pragma unroll 8
        for (int i = 0; i < NC; i++) acc = fmaf(sp[i], w1[i * 64 + threadIdx.x], acc);
        sh[threadIdx.x] = fmaxf(acc, 0.0f);
    }
    __syncthreads();
    float acc = b2[threadIdx.x];
    #pragma unroll 8
    for (int j = 0; j < 64; j++) acc = fmaf(sh[j], w2[j * NC + threadIdx.x], acc);
    g_cw[f][b][threadIdx.x] = __fdividef(1.0f, 1.0f + __expf(-acc));
}

// ---------------- K3: se = sum_c ent(feat)*cw  (DESCENDING slab order) ------
// Serpentine: k_pool ended at the high-address slabs; k_se starts there so its
// first wave hits the ~126 MB that L2 still holds across the launch boundary.
__global__ void k_se(const float* __restrict__ vis, const float* __restrict__ text) {
    int bid   = blockIdx.x;           // 512 blocks
    int slab  = 31 - (bid >> 4);      // reversed (f,b) traversal
    int f     = slab >> 4;
    int b     = slab & 15;
    int chunk = bid & 15;             // 16 chunks of 256 pixels per slab
    int pix   = chunk * 256 + threadIdx.x;
    const float* feat = (f ? text : vis) + (size_t)b * NC * HW + pix;

    __shared__ float scw[NC];
    scw[threadIdx.x] = g_cw[f][b][threadIdx.x];
    __syncthreads();

    float acc = 0.0f;
    #pragma unroll 8
    for (int c = 0; c < NC; c++) {
        float x = feat[(size_t)c * HW];
        acc = fmaf(entropy_val(x), scw[c], acc);
    }
    g_se[f][b][pix] = acc;

    float s = acc, q = acc * acc;
    #pragma unroll
    for (int o = 16; o; o >>= 1) {
        s += __shfl_xor_sync(0xffffffffu, s, o);
        q += __shfl_xor_sync(0xffffffffu, q, o);
    }
    __shared__ float ss[8], sq[8];
    if ((threadIdx.x & 31) == 0) { ss[threadIdx.x >> 5] = s; sq[threadIdx.x >> 5] = q; }
    __syncthreads();
    if (threadIdx.x == 0) {
        float S = 0.0f, Q = 0.0f;
        #pragma unroll
        for (int i = 0; i < 8; i++) { S += ss[i]; Q += sq[i]; }
        g_psum[f][b][chunk] = S;
        g_psq [f][b][chunk] = Q;
    }
}

// ---------------- K4: per-(f,b) threshold + inverse L2 norm (tiny) ----------
__global__ void k_stats() {
    int t = threadIdx.x;
    if (t >= 32) return;
    int f = t >> 4, b = t & 15;
    float S = 0.0f, Q = 0.0f;
    #pragma unroll
    for (int i = 0; i < 16; i++) { S += g_psum[f][b][i]; Q += g_psq[f][b][i]; }
    g_thr[f][b] = S * (0.5f / HW);                  // mean(se)*THRESHOLD (scale-free vs normalize)
    float norm = sqrtf(Q);
    g_inv[f][b] = 1.0f / fmaxf(norm, 1e-12f);
}

// ---------------- K5: enhanced blend (ASCENDING — hits k_se's L2 tail) ------
__global__ void k_out(const float* __restrict__ vis, const float* __restrict__ text,
                      float* __restrict__ out) {
    int idx4 = blockIdx.x * 256 + threadIdx.x;      // 0 .. 4194303
    int pix4 = idx4 & 1023;                         // HW/4 = 1024
    int b    = idx4 >> 18;                          // / (NC*1024)
    float thr_v = g_thr[0][b];
    float thr_t = g_thr[1][b];
    float4 sev = ((const float4*)g_se[0][b])[pix4];
    float4 set = ((const float4*)g_se[1][b])[pix4];
    float4 v = __ldcs(((const float4*)vis) + idx4);   // last use: evict-first
    float4 t = __ldcs(((const float4*)text) + idx4);
    float4 o;
    o.x = (sev.x < thr_v) ? v.x : ((set.x < thr_t) ? t.x : 0.0f);
    o.y = (sev.y < thr_v) ? v.y : ((set.y < thr_t) ? t.y : 0.0f);
    o.z = (sev.z < thr_v) ? v.z : ((set.z < thr_t) ? t.z : 0.0f);
    o.w = (sev.w < thr_v) ? v.w : ((set.w < thr_t) ? t.w : 0.0f);
    __stcs(((float4*)out) + idx4, o);                 // write-once: stream
}

// ---------------- K6: normalized entropy maps into output tail -------------
__global__ void k_ent(float* __restrict__ out) {
    int idx = blockIdx.x * 256 + threadIdx.x;       // 0 .. 131071
    int f   = idx >> 16;
    int rem = idx & 65535;
    int b   = rem >> 12;
    int pix = rem & 4095;
    out[ENH_ELEMS + idx] = g_se[f][b][pix] * g_inv[f][b];
}

// ---------------- launch ----------------
extern "C" void kernel_launch(void* const* d_in, const int* in_sizes, int n_in,
                              void* d_out, int out_size) {
    const float* vis  = (const float*)d_in[0];
    const float* text = (const float*)d_in[1];
    const float* w1   = (const float*)d_in[2];
    const float* b1   = (const float*)d_in[3];
    const float* w2   = (const float*)d_in[4];
    const float* b2   = (const float*)d_in[5];
    float* out = (float*)d_out;

    k_pool <<<2 * NB * NC, 128>>>(vis, text);
    k_mlp  <<<2 * NB, NC>>>(w1, b1, w2, b2);
    k_se   <<<2 * NB * 16, 256>>>(vis, text);
    k_stats<<<1, 32>>>();
    k_out  <<<ENH_ELEMS / 4 / 256, 256>>>(vis, text, out);
    k_ent  <<<2 * ENT_ELEMS / 256, 256>>>(out);
}

// round 9
// speedup vs baseline: 2.0832x; 1.0340x over previous
#include <cuda_runtime.h>
#include <cuda_bf16.h>

// Problem constants
#define NB 16
#define NC 256
#define HW 4096
#define ENH_ELEMS (NB * NC * HW)       // 16777216
#define ENT_ELEMS (NB * HW)            // 65536 per map
#define SE_BLOCKS 512
#define OUT_BLOCKS (ENH_ELEMS / 4 / 256)   // 16384
#define ENT_BLOCKS (2 * ENT_ELEMS / 256)   // 512

// ---------------- scratch (device globals; no allocation) ----------------
__device__ float g_pooled[2][NB][NC];
__device__ float g_cw[2][NB][NC];
__device__ float g_se[2][NB][HW];
__device__ float g_psum[2][NB][16];
__device__ float g_psq[2][NB][16];
__device__ float g_thr[2][NB];
__device__ float g_inv[2][NB];
__device__ unsigned g_ticket;

// ---------------- entropy: log(p+eps) - (1-p)*log(1-p+eps), p=sigmoid(x) ---
// softplus form: log p = -softplus(-x), log(1-p) = -softplus(x)
// softplus(x) = max(x,0) + log(1+exp(-|x|)).  3 MUFU: EX2, LG2, RCP.
__device__ __forceinline__ float entropy_val(float x) {
    float a = fabsf(x);
    float t = __expf(-a);                  // e^{-|x|} in (0,1]
    float l = __logf(1.0f + t);            // log(1+e^{-|x|})
    float inv = __fdividef(1.0f, 1.0f + t);
    bool pos = (x >= 0.0f);
    float p      = pos ? inv        : t * inv;   // sigmoid(x)
    float logp   = pos ? -l         : (x - l);   // log p
    float log1mp = pos ? (-x - l)   : -l;        // log (1-p)
    return logp - (1.0f - p) * log1mp;
}

// ---------------- K1: pooled[b,c] = mean over HW (ascending slab order) -----
__global__ void k_pool(const float* __restrict__ vis, const float* __restrict__ text) {
    int id = blockIdx.x;              // 0..8191, ascending addresses
    int f  = id >> 12;                // /4096 (= NB*NC)
    int bc = id & 4095;
    const float* feat = f ? text : vis;
    const float4* src = (const float4*)(feat + (size_t)bc * HW);
    float acc = 0.0f;
    #pragma unroll 4
    for (int i = threadIdx.x; i < HW / 4; i += 128) {
        float4 v = src[i];
        acc += (v.x + v.y) + (v.z + v.w);
    }
    #pragma unroll
    for (int o = 16; o; o >>= 1) acc += __shfl_xor_sync(0xffffffffu, acc, o);
    __shared__ float s[4];
    if ((threadIdx.x & 31) == 0) s[threadIdx.x >> 5] = acc;
    __syncthreads();
    if (threadIdx.x == 0) {
        float tsum = (s[0] + s[1]) + (s[2] + s[3]);
        int b = bc >> 8, c = bc & 255;
        g_pooled[f][b][c] = tsum * (1.0f / HW);
    }
}

// ---------------- K2: cw = sigmoid(relu(pooled@w1+b1)@w2+b2) ----------------
// also resets the k_se completion ticket (runs before k_se every launch)
__global__ void k_mlp(const float* __restrict__ w1, const float* __restrict__ b1,
                      const float* __restrict__ w2, const float* __restrict__ b2) {
    if (blockIdx.x == 0 && threadIdx.x == 0) g_ticket = 0;
    int f = blockIdx.x >> 4, b = blockIdx.x & 15;
    __shared__ float sp[NC];
    __shared__ float sh[64];
    sp[threadIdx.x] = g_pooled[f][b][threadIdx.x];
    __syncthreads();
    if (threadIdx.x < 64) {
        float acc = b1[threadIdx.x];
        #pragma unroll 8
        for (int i = 0; i < NC; i++) acc = fmaf(sp[i], w1[i * 64 + threadIdx.x], acc);
        sh[threadIdx.x] = fmaxf(acc, 0.0f);
    }
    __syncthreads();
    float acc = b2[threadIdx.x];
    #pragma unroll 8
    for (int j = 0; j < 64; j++) acc = fmaf(sh[j], w2[j * NC + threadIdx.x], acc);
    g_cw[f][b][threadIdx.x] = __fdividef(1.0f, 1.0f + __expf(-acc));
}

// ---------------- K3: se = sum_c ent(feat)*cw  (DESCENDING slab order) ------
// Serpentine: k_pool ended at the high-address slabs; k_se starts there so its
// first wave hits what L2 still holds across the launch boundary.
// The LAST block to finish also computes per-(f,b) thr + inv norm (was k_stats).
__global__ void k_se(const float* __restrict__ vis, const float* __restrict__ text) {
    int bid   = blockIdx.x;           // 512 blocks
    int slab  = 31 - (bid >> 4);      // reversed (f,b) traversal
    int f     = slab >> 4;
    int b     = slab & 15;
    int chunk = bid & 15;             // 16 chunks of 256 pixels per slab
    int pix   = chunk * 256 + threadIdx.x;
    const float* feat = (f ? text : vis) + (size_t)b * NC * HW + pix;

    __shared__ float scw[NC];
    scw[threadIdx.x] = g_cw[f][b][threadIdx.x];
    __syncthreads();

    float acc = 0.0f;
    #pragma unroll 8
    for (int c = 0; c < NC; c++) {
        float x = feat[(size_t)c * HW];
        acc = fmaf(entropy_val(x), scw[c], acc);
    }
    g_se[f][b][pix] = acc;

    float s = acc, q = acc * acc;
    #pragma unroll
    for (int o = 16; o; o >>= 1) {
        s += __shfl_xor_sync(0xffffffffu, s, o);
        q += __shfl_xor_sync(0xffffffffu, q, o);
    }
    __shared__ float ss[8], sq[8];
    __shared__ bool last;
    if ((threadIdx.x & 31) == 0) { ss[threadIdx.x >> 5] = s; sq[threadIdx.x >> 5] = q; }
    __syncthreads();
    if (threadIdx.x == 0) {
        float S = 0.0f, Q = 0.0f;
        #pragma unroll
        for (int i = 0; i < 8; i++) { S += ss[i]; Q += sq[i]; }
        g_psum[f][b][chunk] = S;
        g_psq [f][b][chunk] = Q;
        __threadfence();                               // publish partials
        unsigned t = atomicAdd(&g_ticket, 1u);
        last = (t == SE_BLOCKS - 1);
    }
    __syncthreads();
    if (last && threadIdx.x < 32) {                    // final stats (ex-k_stats)
        int ff = threadIdx.x >> 4, bb = threadIdx.x & 15;
        float S = 0.0f, Q = 0.0f;
        #pragma unroll
        for (int i = 0; i < 16; i++) { S += g_psum[ff][bb][i]; Q += g_psq[ff][bb][i]; }
        g_thr[ff][bb] = S * (0.5f / HW);               // mean(se)*0.5 (scale-free vs normalize)
        g_inv[ff][bb] = 1.0f / fmaxf(sqrtf(Q), 1e-12f);
    }
}

// ---------------- K4: blend (ASC, hits k_se's L2 tail) + ent tail blocks ----
__global__ void k_out(const float* __restrict__ vis, const float* __restrict__ text,
                      float* __restrict__ out) {
    if (blockIdx.x >= OUT_BLOCKS) {
        // normalized entropy maps (ex-k_ent)
        int idx = (blockIdx.x - OUT_BLOCKS) * 256 + threadIdx.x;   // 0..131071
        int f   = idx >> 16;
        int rem = idx & 65535;
        int b   = rem >> 12;
        int pix = rem & 4095;
        __stcs(out + ENH_ELEMS + idx, g_se[f][b][pix] * g_inv[f][b]);
        return;
    }
    int idx4 = blockIdx.x * 256 + threadIdx.x;      // 0 .. 4194303
    int pix4 = idx4 & 1023;                         // HW/4 = 1024
    int b    = idx4 >> 18;                          // / (NC*1024)
    float thr_v = g_thr[0][b];
    float thr_t = g_thr[1][b];
    float4 sev = ((const float4*)g_se[0][b])[pix4];
    float4 set = ((const float4*)g_se[1][b])[pix4];
    float4 v = __ldcs(((const float4*)vis) + idx4);   // last use: evict-first
    float4 t = __ldcs(((const float4*)text) + idx4);
    float4 o;
    o.x = (sev.x < thr_v) ? v.x : ((set.x < thr_t) ? t.x : 0.0f);
    o.y = (sev.y < thr_v) ? v.y : ((set.y < thr_t) ? t.y : 0.0f);
    o.z = (sev.z < thr_v) ? v.z : ((set.z < thr_t) ? t.z : 0.0f);
    o.w = (sev.w < thr_v) ? v.w : ((set.w < thr_t) ? t.w : 0.0f);
    __stcs(((float4*)out) + idx4, o);                 // write-once: stream
}

// ---------------- launch ----------------
extern "C" void kernel_launch(void* const* d_in, const int* in_sizes, int n_in,
                              void* d_out, int out_size) {
    const float* vis  = (const float*)d_in[0];
    const float* text = (const float*)d_in[1];
    const float* w1   = (const float*)d_in[2];
    const float* b1   = (const float*)d_in[3];
    const float* w2   = (const float*)d_in[4];
    const float* b2   = (const float*)d_in[5];
    float* out = (float*)d_out;

    k_pool<<<2 * NB * NC, 128>>>(vis, text);
    k_mlp <<<2 * NB, NC>>>(w1, b1, w2, b2);
    k_se  <<<SE_BLOCKS, 256>>>(vis, text);
    k_out <<<OUT_BLOCKS + ENT_BLOCKS, 256>>>(vis, text, out);
}